// round 14
// baseline (speedup 1.0000x reference)
#include <cuda_runtime.h>
#include <math.h>

#define H 8192
#define NSPLIT 128                     // slices (work items per column block)
#define ROWS_PER_ITEM (H / NSPLIT)     // 64
#define COLBLKS (H / (256 * 4))        // 8
#define NITEMS (COLBLKS * NSPLIT)      // 1024
#define NCTAS 512
#define UNROLL 8
#define CACHE_LIM 48                   // local row idx < 48 (of 64) -> L2-cached (~100 MB resident)
#define K3_BLOCKS 128
#define K3_COLS 64
#define K3_GRPS 4
#define K3_PER_GRP (NSPLIT / K3_GRPS)  // 32

// Scratch (no cudaMalloc allowed)
__device__ float g_part[NSPLIT * H];        // layer-2 partials (4 MB, L2)
__device__ float g_pen_part[K3_BLOCKS * 8]; // head partials
__device__ int   g_done_cnt;                // k3 completion counter
__device__ int   g_item = NCTAS;            // work-steal counter (k3 resets to NCTAS)

// ---- k2: persistent CTAs pull (colblk, slice) items; per item: h1 recompute +
//      cached/streamed compaction + GEMV partial. Output independent of schedule. ----
__global__ void __launch_bounds__(256, 4) k2_fused(const float* __restrict__ state,
                                                   const float* __restrict__ W1,
                                                   const float* __restrict__ b1,
                                                   const float* __restrict__ W2) {
    __shared__ float s[42];
    __shared__ float xs[ROWS_PER_ITEM];
    __shared__ int   ridx[ROWS_PER_ITEM];
    __shared__ int   c1[2], c2[2];
    __shared__ int   nxt;
    int t = threadIdx.x;
    int lane = t & 31, wid = t >> 5;
    if (t < 42) s[t] = state[t];
    __syncthreads();

    int item = blockIdx.x;                 // first item deterministic-ish; rest stolen
    while (item < NITEMS) {
        int colblk = item & (COLBLKS - 1);
        int slice  = item >> 3;            // item / COLBLKS
        int r0 = slice * ROWS_PER_ITEM;

        // threads 0..63 (warps 0,1): h1 + classification
        float v = 0.0f;
        bool cach = false, strm = false;
        if (t < ROWS_PER_ITEM) {
            float acc = b1[r0 + t];
            #pragma unroll
            for (int k = 0; k < 42; k++)
                acc = fmaf(s[k], __ldg(W1 + (size_t)k * H + r0 + t), acc);
            v = fmaxf(acc, 0.0f);
            cach = (v > 0.0f) && (t <  CACHE_LIM);
            strm = (v > 0.0f) && (t >= CACHE_LIM);
        }
        unsigned m1 = __ballot_sync(0xFFFFFFFF, cach);
        unsigned m2 = __ballot_sync(0xFFFFFFFF, strm);
        if (lane == 0 && wid < 2) { c1[wid] = __popc(m1); c2[wid] = __popc(m2); }
        __syncthreads();
        int nc = c1[0] + c1[1];
        int ns = c2[0] + c2[1];
        unsigned lt = (1u << lane) - 1;
        if (cach) {
            int off = __popc(m1 & lt) + (wid == 1 ? c1[0] : 0);
            xs[off] = v;  ridx[off] = r0 + t;
        }
        if (strm) {
            int off = nc + __popc(m2 & lt) + (wid == 1 ? c2[0] : 0);
            xs[off] = v;  ridx[off] = r0 + t;
        }
        __syncthreads();

        int c = (colblk * 256 + t) * 4;
        float4 acc = make_float4(0.f, 0.f, 0.f, 0.f);

        // cached list: default caching -> L2-resident across graph replays
        int nc8 = nc & ~(UNROLL - 1);
        for (int rb = 0; rb < nc8; rb += UNROLL) {
            float4 w[UNROLL];
            #pragma unroll
            for (int u = 0; u < UNROLL; u++)
                w[u] = __ldg(reinterpret_cast<const float4*>(
                           W2 + (size_t)ridx[rb + u] * H + c));
            #pragma unroll
            for (int u = 0; u < UNROLL; u++) {
                float xv = xs[rb + u];
                acc.x = fmaf(xv, w[u].x, acc.x);
                acc.y = fmaf(xv, w[u].y, acc.y);
                acc.z = fmaf(xv, w[u].z, acc.z);
                acc.w = fmaf(xv, w[u].w, acc.w);
            }
        }
        for (int r = nc8; r < nc; r++) {
            float4 w = __ldg(reinterpret_cast<const float4*>(
                           W2 + (size_t)ridx[r] * H + c));
            float xv = xs[r];
            acc.x = fmaf(xv, w.x, acc.x);  acc.y = fmaf(xv, w.y, acc.y);
            acc.z = fmaf(xv, w.z, acc.z);  acc.w = fmaf(xv, w.w, acc.w);
        }

        // streamed list: evict-first, never displaces the resident set
        int ne = nc + ns;
        int ns8 = nc + ((ne - nc) & ~(UNROLL - 1));
        for (int rb = nc; rb < ns8; rb += UNROLL) {
            float4 w[UNROLL];
            #pragma unroll
            for (int u = 0; u < UNROLL; u++)
                w[u] = __ldcs(reinterpret_cast<const float4*>(
                           W2 + (size_t)ridx[rb + u] * H + c));
            #pragma unroll
            for (int u = 0; u < UNROLL; u++) {
                float xv = xs[rb + u];
                acc.x = fmaf(xv, w[u].x, acc.x);
                acc.y = fmaf(xv, w[u].y, acc.y);
                acc.z = fmaf(xv, w[u].z, acc.z);
                acc.w = fmaf(xv, w[u].w, acc.w);
            }
        }
        for (int r = ns8; r < ne; r++) {
            float4 w = __ldcs(reinterpret_cast<const float4*>(
                           W2 + (size_t)ridx[r] * H + c));
            float xv = xs[r];
            acc.x = fmaf(xv, w.x, acc.x);  acc.y = fmaf(xv, w.y, acc.y);
            acc.z = fmaf(xv, w.z, acc.z);  acc.w = fmaf(xv, w.w, acc.w);
        }

        *reinterpret_cast<float4*>(g_part + (size_t)slice * H + c) = acc;

        // steal next item
        __syncthreads();
        if (t == 0) nxt = atomicAdd(&g_item, 1);
        __syncthreads();
        item = nxt;
    }
}

// ---- k3: 128-block parallel reduce (4 groups x 32 partials) + W3 head + softmax ----
__global__ void __launch_bounds__(256) k3(const float* __restrict__ state,
                                          const float* __restrict__ b2,
                                          const float* __restrict__ W3,
                                          const float* __restrict__ b3,
                                          float* __restrict__ out) {
    __shared__ float gsum[K3_GRPS][K3_COLS];
    __shared__ float red[K3_COLS][8];
    __shared__ int   flag;
    int t = threadIdx.x;
    int cl = t & (K3_COLS - 1);
    int gp = t >> 6;
    int j = blockIdx.x * K3_COLS + cl;

    // reset work-steal counter for the next graph replay (any single thread)
    if (blockIdx.x == 0 && t == 0) g_item = NCTAS;

    // sum 32 partials in two MLP-16 batches
    float a0 = 0.f, a1 = 0.f, a2 = 0.f, a3 = 0.f;
    #pragma unroll
    for (int half = 0; half < 2; half++) {
        float p[16];
        #pragma unroll
        for (int u = 0; u < 16; u++)
            p[u] = g_part[(size_t)(gp * K3_PER_GRP + half * 16 + u) * H + j];
        #pragma unroll
        for (int u = 0; u < 16; u += 4) {
            a0 += p[u]; a1 += p[u + 1]; a2 += p[u + 2]; a3 += p[u + 3];
        }
    }
    gsum[gp][cl] = (a0 + a1) + (a2 + a3);
    __syncthreads();

    if (t < K3_COLS) {
        float h2 = fmaxf(b2[j] + ((gsum[0][cl] + gsum[1][cl]) +
                                  (gsum[2][cl] + gsum[3][cl])), 0.0f);
        float4 w0 = *reinterpret_cast<const float4*>(W3 + (size_t)j * 8);
        float4 w1 = *reinterpret_cast<const float4*>(W3 + (size_t)j * 8 + 4);
        red[cl][0] = h2 * w0.x;  red[cl][1] = h2 * w0.y;
        red[cl][2] = h2 * w0.z;  red[cl][3] = h2 * w0.w;
        red[cl][4] = h2 * w1.x;  red[cl][5] = h2 * w1.y;
        red[cl][6] = h2 * w1.z;  red[cl][7] = h2 * w1.w;
    }
    __syncthreads();

    for (int stride = K3_COLS / 2; stride > 0; stride >>= 1) {
        if (t < stride) {
            #pragma unroll
            for (int n = 0; n < 8; n++) red[t][n] += red[t + stride][n];
        }
        __syncthreads();
    }
    if (t < 8) g_pen_part[blockIdx.x * 8 + t] = red[0][t];

    __syncthreads();
    __threadfence();
    if (t == 0) {
        int old = atomicAdd(&g_done_cnt, 1);
        flag = (old == K3_BLOCKS - 1);
        if (flag) g_done_cnt = 0;   // reset for graph replay
    }
    __syncthreads();
    if (!flag) return;
    __threadfence();

    __shared__ float psum[8][8];
    if (t < 64) {
        int n = t & 7, ch = t >> 3;
        float a = 0.0f;
        #pragma unroll
        for (int b = 0; b < K3_BLOCKS / 8; b++)
            a += g_pen_part[(ch * (K3_BLOCKS / 8) + b) * 8 + n];
        psum[ch][n] = a;
    }
    __syncthreads();

    if (t == 0) {
        float pens[8];
        #pragma unroll
        for (int n = 0; n < 8; n++) {
            float a = b3[n];
            #pragma unroll
            for (int ch = 0; ch < 8; ch++) a += psum[ch][n];
            pens[n] = a;
        }
        float value = pens[7];
        bool legal[7];
        float mx = -INFINITY;
        #pragma unroll
        for (int n = 0; n < 7; n++) {
            legal[n] = (state[n] == 0.0f);
            if (legal[n] && pens[n] > mx) mx = pens[n];
        }
        float e[7];
        float sum = 0.0f;
        #pragma unroll
        for (int n = 0; n < 7; n++) {
            e[n] = legal[n] ? expf(pens[n] - mx) : 0.0f;
            sum += e[n];
        }
        float inv = 1.0f / sum;
        out[0] = value;
        #pragma unroll
        for (int n = 0; n < 7; n++) out[1 + n] = e[n] * inv;
    }
}

extern "C" void kernel_launch(void* const* d_in, const int* in_sizes, int n_in,
                              void* d_out, int out_size) {
    const float* state = (const float*)d_in[0];
    const float* W1    = (const float*)d_in[1];
    const float* b1    = (const float*)d_in[2];
    const float* W2    = (const float*)d_in[3];
    const float* b2    = (const float*)d_in[4];
    const float* W3    = (const float*)d_in[5];
    const float* b3    = (const float*)d_in[6];
    float* out = (float*)d_out;

    k2_fused<<<NCTAS, 256>>>(state, W1, b1, W2);   // 512 persistent CTAs, 1024 items

    k3<<<K3_BLOCKS, 256>>>(state, b2, W3, b3, out);
}

// round 15
// speedup vs baseline: 1.3648x; 1.3648x over previous
#include <cuda_runtime.h>
#include <math.h>

#define H 8192
#define NSPLIT 64
#define ROWS_PER_SPLIT (H / NSPLIT)   // 128
#define COLBLKS (H / (256 * 4))       // 8
#define UNROLL 8
#define CACHE_LIM 64                   // local row idx < 64 -> L2-cached (~67 MB resident)
#define K3_BLOCKS 128
#define K3_COLS 64                     // columns per k3 block
#define K3_GRPS 4                      // partial-groups per column
#define K3_PER_GRP (NSPLIT / K3_GRPS)  // 16

// Scratch (no cudaMalloc allowed)
__device__ float g_part[NSPLIT * H];        // layer-2 partials (2 MB, L2)
__device__ float g_pen_part[K3_BLOCKS * 8]; // head partials
__device__ int   g_done_cnt;                // k3 completion counter

// ---- k2: fused h1-recompute + two-list compaction (cached / streamed) + GEMV ----
__global__ void __launch_bounds__(256, 4) k2_fused(const float* __restrict__ state,
                                                   const float* __restrict__ W1,
                                                   const float* __restrict__ b1,
                                                   const float* __restrict__ W2) {
    __shared__ float s[42];
    __shared__ float xs[ROWS_PER_SPLIT];
    __shared__ int   ridx[ROWS_PER_SPLIT];
    __shared__ int   c1[4], c2[4];
    int t = threadIdx.x;
    int lane = t & 31, wid = t >> 5;
    if (t < 42) s[t] = state[t];
    __syncthreads();

    int r0 = blockIdx.y * ROWS_PER_SPLIT;

    float v = 0.0f;
    bool cach = false, strm = false;
    if (t < ROWS_PER_SPLIT) {
        float acc = b1[r0 + t];
        #pragma unroll
        for (int k = 0; k < 42; k++)
            acc = fmaf(s[k], __ldg(W1 + (size_t)k * H + r0 + t), acc);
        v = fmaxf(acc, 0.0f);
        cach = (v > 0.0f) && (t <  CACHE_LIM);
        strm = (v > 0.0f) && (t >= CACHE_LIM);
    }
    unsigned m1 = __ballot_sync(0xFFFFFFFF, cach);
    unsigned m2 = __ballot_sync(0xFFFFFFFF, strm);
    if (lane == 0 && wid < 4) { c1[wid] = __popc(m1); c2[wid] = __popc(m2); }
    __syncthreads();
    int nc = c1[0] + c1[1] + c1[2] + c1[3];
    int ns = c2[0] + c2[1] + c2[2] + c2[3];
    unsigned lt = (1u << lane) - 1;
    if (cach) {
        int off = __popc(m1 & lt);
        for (int w = 0; w < 4; w++) if (w < wid) off += c1[w];
        xs[off] = v;  ridx[off] = r0 + t;
    }
    if (strm) {
        int off = nc + __popc(m2 & lt);
        for (int w = 0; w < 4; w++) if (w < wid) off += c2[w];
        xs[off] = v;  ridx[off] = r0 + t;
    }
    __syncthreads();

    int c = (blockIdx.x * 256 + t) * 4;
    float4 acc = make_float4(0.f, 0.f, 0.f, 0.f);

    // cached list: default caching -> L2-resident across graph replays
    int nc8 = nc & ~(UNROLL - 1);
    for (int rb = 0; rb < nc8; rb += UNROLL) {
        float4 w[UNROLL];
        #pragma unroll
        for (int u = 0; u < UNROLL; u++)
            w[u] = __ldg(reinterpret_cast<const float4*>(
                       W2 + (size_t)ridx[rb + u] * H + c));
        #pragma unroll
        for (int u = 0; u < UNROLL; u++) {
            float xv = xs[rb + u];
            acc.x = fmaf(xv, w[u].x, acc.x);
            acc.y = fmaf(xv, w[u].y, acc.y);
            acc.z = fmaf(xv, w[u].z, acc.z);
            acc.w = fmaf(xv, w[u].w, acc.w);
        }
    }
    for (int r = nc8; r < nc; r++) {
        float4 w = __ldg(reinterpret_cast<const float4*>(
                       W2 + (size_t)ridx[r] * H + c));
        float xv = xs[r];
        acc.x = fmaf(xv, w.x, acc.x);  acc.y = fmaf(xv, w.y, acc.y);
        acc.z = fmaf(xv, w.z, acc.z);  acc.w = fmaf(xv, w.w, acc.w);
    }

    // streamed list: evict-first, never displaces the resident set
    int ne = nc + ns;
    int ns8 = nc + ((ne - nc) & ~(UNROLL - 1));
    for (int rb = nc; rb < ns8; rb += UNROLL) {
        float4 w[UNROLL];
        #pragma unroll
        for (int u = 0; u < UNROLL; u++)
            w[u] = __ldcs(reinterpret_cast<const float4*>(
                       W2 + (size_t)ridx[rb + u] * H + c));
        #pragma unroll
        for (int u = 0; u < UNROLL; u++) {
            float xv = xs[rb + u];
            acc.x = fmaf(xv, w[u].x, acc.x);
            acc.y = fmaf(xv, w[u].y, acc.y);
            acc.z = fmaf(xv, w[u].z, acc.z);
            acc.w = fmaf(xv, w[u].w, acc.w);
        }
    }
    for (int r = ns8; r < ne; r++) {
        float4 w = __ldcs(reinterpret_cast<const float4*>(
                       W2 + (size_t)ridx[r] * H + c));
        float xv = xs[r];
        acc.x = fmaf(xv, w.x, acc.x);  acc.y = fmaf(xv, w.y, acc.y);
        acc.z = fmaf(xv, w.z, acc.z);  acc.w = fmaf(xv, w.w, acc.w);
    }

    *reinterpret_cast<float4*>(g_part + (size_t)blockIdx.y * H + c) = acc;
}

// ---- k3: 128-block parallel reduce (4-way partial split) + W3 head + softmax ----
__global__ void __launch_bounds__(256) k3(const float* __restrict__ state,
                                          const float* __restrict__ b2,
                                          const float* __restrict__ W3,
                                          const float* __restrict__ b3,
                                          float* __restrict__ out) {
    __shared__ float gsum[K3_GRPS][K3_COLS];
    __shared__ float red[K3_COLS][8];
    __shared__ int   flag;
    int t = threadIdx.x;
    int cl = t & (K3_COLS - 1);
    int gp = t >> 6;
    int j = blockIdx.x * K3_COLS + cl;

    // sum 16 partials (independent loads — deep MLP)
    float p[K3_PER_GRP];
    #pragma unroll
    for (int u = 0; u < K3_PER_GRP; u++)
        p[u] = g_part[(size_t)(gp * K3_PER_GRP + u) * H + j];
    float a0 = 0.f, a1 = 0.f, a2 = 0.f, a3 = 0.f;
    #pragma unroll
    for (int u = 0; u < K3_PER_GRP; u += 4) {
        a0 += p[u]; a1 += p[u + 1]; a2 += p[u + 2]; a3 += p[u + 3];
    }
    gsum[gp][cl] = (a0 + a1) + (a2 + a3);
    __syncthreads();

    if (t < K3_COLS) {
        // fixed combine order -> deterministic
        float h2 = fmaxf(b2[j] + ((gsum[0][cl] + gsum[1][cl]) +
                                  (gsum[2][cl] + gsum[3][cl])), 0.0f);
        float4 w0 = *reinterpret_cast<const float4*>(W3 + (size_t)j * 8);
        float4 w1 = *reinterpret_cast<const float4*>(W3 + (size_t)j * 8 + 4);
        red[cl][0] = h2 * w0.x;  red[cl][1] = h2 * w0.y;
        red[cl][2] = h2 * w0.z;  red[cl][3] = h2 * w0.w;
        red[cl][4] = h2 * w1.x;  red[cl][5] = h2 * w1.y;
        red[cl][6] = h2 * w1.z;  red[cl][7] = h2 * w1.w;
    }
    __syncthreads();

    for (int stride = K3_COLS / 2; stride > 0; stride >>= 1) {
        if (t < stride) {
            #pragma unroll
            for (int n = 0; n < 8; n++) red[t][n] += red[t + stride][n];
        }
        __syncthreads();
    }
    if (t < 8) g_pen_part[blockIdx.x * 8 + t] = red[0][t];

    // last-arriver among the 128 blocks does bias + value + masked softmax
    __syncthreads();
    __threadfence();
    if (t == 0) {
        int old = atomicAdd(&g_done_cnt, 1);
        flag = (old == K3_BLOCKS - 1);
        if (flag) g_done_cnt = 0;   // reset for graph replay
    }
    __syncthreads();
    if (!flag) return;
    __threadfence();   // all 128 g_pen_part writes visible

    // parallel pen sum: 64 threads = 8 outputs x 8 chunks of 16 blocks
    __shared__ float psum[8][8];
    if (t < 64) {
        int n = t & 7, ch = t >> 3;
        float a = 0.0f;
        #pragma unroll
        for (int b = 0; b < K3_BLOCKS / 8; b++)
            a += g_pen_part[(ch * (K3_BLOCKS / 8) + b) * 8 + n];
        psum[ch][n] = a;
    }
    __syncthreads();

    if (t == 0) {
        float pens[8];
        #pragma unroll
        for (int n = 0; n < 8; n++) {
            float a = b3[n];
            #pragma unroll
            for (int ch = 0; ch < 8; ch++) a += psum[ch][n];
            pens[n] = a;
        }
        float value = pens[7];
        bool legal[7];
        float mx = -INFINITY;
        #pragma unroll
        for (int n = 0; n < 7; n++) {
            legal[n] = (state[n] == 0.0f);
            if (legal[n] && pens[n] > mx) mx = pens[n];
        }
        float e[7];
        float sum = 0.0f;
        #pragma unroll
        for (int n = 0; n < 7; n++) {
            e[n] = legal[n] ? expf(pens[n] - mx) : 0.0f;
            sum += e[n];
        }
        float inv = 1.0f / sum;
        out[0] = value;
        #pragma unroll
        for (int n = 0; n < 7; n++) out[1 + n] = e[n] * inv;
    }
}

extern "C" void kernel_launch(void* const* d_in, const int* in_sizes, int n_in,
                              void* d_out, int out_size) {
    const float* state = (const float*)d_in[0];
    const float* W1    = (const float*)d_in[1];
    const float* b1    = (const float*)d_in[2];
    const float* W2    = (const float*)d_in[3];
    const float* b2    = (const float*)d_in[4];
    const float* W3    = (const float*)d_in[5];
    const float* b3    = (const float*)d_in[6];
    float* out = (float*)d_out;

    dim3 g2(COLBLKS, NSPLIT);             // (8, 64) = 512 blocks
    k2_fused<<<g2, 256>>>(state, W1, b1, W2);

    k3<<<K3_BLOCKS, 256>>>(state, b2, W3, b3, out);
}